// round 5
// baseline (speedup 1.0000x reference)
#include <cuda_runtime.h>
#include <cuda_bf16.h>
#include <cuda_fp8.h>
#include <cstdint>

// ---------------------------------------------------------------------------
// DeepFM: out = bias + first + second + MLP(emb)
// FP8 e4m3 mma.sync GEMMs with 64x64 warp tiles (CTA 256x128, BK=64).
// Activations/weights stored as fp8 of (value*64); acc = 4096*true;
// epilogue stores fp8(acc/64). FM terms exact fp32.
// ---------------------------------------------------------------------------

namespace cfg {
constexpr int B  = 16384;
constexpr int F  = 26;
constexpr int V  = 100000;
constexpr int D  = 64;
constexpr int ND = 13;
constexpr int H1 = 1024;
constexpr int H2 = 512;
constexpr int H3 = 256;
constexpr int K0 = (F + 1) * D;  // 1728
}

constexpr float SCALE = 64.f;
constexpr float INV_SCALE = 1.f / 64.f;

// ------------------------- scratch (device globals) ------------------------
__device__ uint8_t g_h  [(size_t)cfg::B * cfg::K0];   // fp8 e4m3, x64
__device__ uint8_t g_h1 [(size_t)cfg::B * cfg::H1];
__device__ uint8_t g_h2 [(size_t)cfg::B * cfg::H2];
__device__ uint8_t g_h3 [(size_t)cfg::B * cfg::H3];
__device__ uint8_t g_Wt1[cfg::H1 * cfg::K0];          // [N,K] fp8, x64
__device__ uint8_t g_Wt2[cfg::H2 * cfg::H1];
__device__ uint8_t g_Wt3[cfg::H3 * cfg::H2];

__device__ __forceinline__ uint8_t to_fp8(float v) {
    return (uint8_t)__nv_cvt_float_to_fp8(v, __NV_SATFINITE, __NV_E4M3);
}
__device__ __forceinline__ float from_fp8(uint8_t v) {
    return __half2float(__nv_cvt_fp8_to_halfraw(v, __NV_E4M3));
}

// ------------------------- weight transpose+convert ------------------------
__global__ __launch_bounds__(256) void transpose_convert(
    const float* __restrict__ in, uint8_t* __restrict__ out, int K, int N) {
    __shared__ float t[32][33];
    const int tx = threadIdx.x & 31, ty = threadIdx.x >> 5;  // 32x8
    const int n0 = blockIdx.x * 32, k0 = blockIdx.y * 32;
#pragma unroll
    for (int j = 0; j < 4; j++)
        t[ty + j * 8][tx] = in[(size_t)(k0 + ty + j * 8) * N + n0 + tx];
    __syncthreads();
#pragma unroll
    for (int j = 0; j < 4; j++)
        out[(size_t)(n0 + ty + j * 8) * K + k0 + tx] =
            to_fp8(t[tx][ty + j * 8] * SCALE);
}

// ------------------------- embed + FM (fp32 exact) -------------------------
__global__ __launch_bounds__(256) void embed_kernel(
    const float* __restrict__ dense, const int* __restrict__ sidx,
    const float* __restrict__ bias, const float* __restrict__ emb_tables,
    const float* __restrict__ lin_tables, const float* __restrict__ Wd,
    const float* __restrict__ Wld, const float* __restrict__ bld,
    float* __restrict__ out) {
    const int sub = threadIdx.x >> 6;
    const int d   = threadIdx.x & 63;
    const int row = blockIdx.x * 4 + sub;

    const float* dr = dense + (size_t)row * cfg::ND;

    int idx[cfg::F];
#pragma unroll
    for (int f = 0; f < cfg::F; f++) idx[f] = __ldg(sidx + (size_t)row * cfg::F + f);

    float ev[cfg::F];
#pragma unroll
    for (int f = 0; f < cfg::F; f++)
        ev[f] = __ldg(emb_tables + ((size_t)f * cfg::V + idx[f]) * cfg::D + d);

    float lin = 0.f;
    if (d < cfg::F) lin = __ldg(lin_tables + (size_t)d * cfg::V + idx[d]);

    float de = 0.f;
#pragma unroll
    for (int i = 0; i < cfg::ND; i++) de += dr[i] * Wd[i * cfg::D + d];

    float s  = de;
    float sq = de * de;
    uint8_t* hrow = g_h + (size_t)row * cfg::K0;
    hrow[d] = to_fp8(de * SCALE);

#pragma unroll
    for (int f = 0; f < cfg::F; f++) {
        float e = ev[f];
        s  += e;
        sq += e * e;
        hrow[(size_t)(f + 1) * cfg::D + d] = to_fp8(e * SCALE);
    }

    float val = 0.5f * (s * s - sq) + lin;
    if (d < cfg::ND) val += dr[d] * Wld[d];

#pragma unroll
    for (int o = 16; o > 0; o >>= 1)
        val += __shfl_down_sync(0xffffffffu, val, o);

    __shared__ float red[8];
    if ((threadIdx.x & 31) == 0) red[threadIdx.x >> 5] = val;
    __syncthreads();
    if (d == 0)
        out[row] = bias[0] + bld[0] + red[sub * 2] + red[sub * 2 + 1];
}

// ------------------------- FP8 tensor-core GEMM ----------------------------
// CTA tile 256x128, warp grid 4(M) x 2(N) -> warp tile 64x64, BK=64.
#define BM 256
#define BN 128
#define BK 64
#define NS 3
#define TSTR 80                     // 64B row + 16B pad
#define A_ST (BM * TSTR)            // 20480 B / stage
#define B_ST (BN * TSTR)            // 10240 B / stage
#define STAGE_B (A_ST + B_ST)
#define GEMM_SMEM (NS * STAGE_B)    // 92160 B

__device__ __forceinline__ uint32_t smem_u32(const void* p) {
    return (uint32_t)__cvta_generic_to_shared(p);
}
__device__ __forceinline__ void cp16(uint32_t s, const void* g) {
    asm volatile("cp.async.cg.shared.global [%0], [%1], 16;\n" ::"r"(s), "l"(g));
}
__device__ __forceinline__ void cp_commit() {
    asm volatile("cp.async.commit_group;\n");
}
template <int N> __device__ __forceinline__ void cp_wait() {
    asm volatile("cp.async.wait_group %0;\n" ::"n"(N));
}
__device__ __forceinline__ void ldm_x4(uint32_t a, uint32_t& r0, uint32_t& r1,
                                       uint32_t& r2, uint32_t& r3) {
    asm volatile("ldmatrix.sync.aligned.m8n8.x4.shared.b16 {%0,%1,%2,%3}, [%4];\n"
                 : "=r"(r0), "=r"(r1), "=r"(r2), "=r"(r3)
                 : "r"(a));
}
__device__ __forceinline__ void mma_fp8(float* c, const uint32_t* a,
                                        uint32_t b0, uint32_t b1) {
    asm volatile(
        "mma.sync.aligned.m16n8k32.row.col.f32.e4m3.e4m3.f32 "
        "{%0,%1,%2,%3}, {%4,%5,%6,%7}, {%8,%9}, {%0,%1,%2,%3};\n"
        : "+f"(c[0]), "+f"(c[1]), "+f"(c[2]), "+f"(c[3])
        : "r"(a[0]), "r"(a[1]), "r"(a[2]), "r"(a[3]), "r"(b0), "r"(b1));
}

__global__ __launch_bounds__(256, 1) void gemm_relu_fp8(
    const uint8_t* __restrict__ A, const uint8_t* __restrict__ Wt,
    uint8_t* __restrict__ C, int M, int N, int K)
{
    extern __shared__ __align__(16) uint8_t smem[];

    const int tid  = threadIdx.x;
    const int bm   = blockIdx.y * BM;
    const int bn   = blockIdx.x * BN;
    const int wid  = tid >> 5;
    const int lane = tid & 31;
    const int wm   = (wid & 3) * 64;   // 4 warps over M
    const int wn   = (wid >> 2) * 64;  // 2 warps over N

    auto load_tiles = [&](int buf, int kofs) {
        uint8_t* sA = smem + buf * STAGE_B;
        uint8_t* sB = sA + A_ST;
        // A: 256 rows x 4 chunks of 16B (1024 chunks, 4 iters)
#pragma unroll
        for (int it = 0; it < 4; it++) {
            int c = tid + it * 256;
            int r = c >> 2, cg = c & 3;
            cp16(smem_u32(sA + r * TSTR + cg * 16),
                 A + (size_t)(bm + r) * K + kofs + cg * 16);
        }
        // B: 128 n-rows x 4 chunks of 16B (512 chunks, 2 iters)
#pragma unroll
        for (int it = 0; it < 2; it++) {
            int c = tid + it * 256;
            int r = c >> 2, cg = c & 3;
            cp16(smem_u32(sB + r * TSTR + cg * 16),
                 Wt + (size_t)(bn + r) * K + kofs + cg * 16);
        }
    };

    float acc[4][8][4];
#pragma unroll
    for (int i = 0; i < 4; i++)
#pragma unroll
        for (int j = 0; j < 8; j++)
#pragma unroll
            for (int k = 0; k < 4; k++) acc[i][j][k] = 0.f;

    const int KT = K / BK;

#pragma unroll
    for (int s = 0; s < NS - 1; s++) {
        load_tiles(s, s * BK);
        cp_commit();
    }

    for (int kt = 0; kt < KT; kt++) {
        const int buf = kt % NS;
        cp_wait<NS - 2>();
        __syncthreads();

        const int pf = kt + NS - 1;
        if (pf < KT) load_tiles(pf % NS, pf * BK);
        cp_commit();

        uint8_t* sA = smem + buf * STAGE_B;
        uint8_t* sB = sA + A_ST;
#pragma unroll
        for (int ks = 0; ks < 2; ks++) {         // two k32 steps
            uint32_t af[4][4];
#pragma unroll
            for (int mi = 0; mi < 4; mi++) {
                int r = wm + mi * 16 + (lane & 15);
                int cb = ks * 32 + (lane >> 4) * 16;
                ldm_x4(smem_u32(sA + r * TSTR + cb),
                       af[mi][0], af[mi][1], af[mi][2], af[mi][3]);
            }
            uint32_t bf[4][4];
#pragma unroll
            for (int nj = 0; nj < 4; nj++) {
                int r = wn + nj * 16 + (lane & 15);
                int cb = ks * 32 + (lane >> 4) * 16;
                ldm_x4(smem_u32(sB + r * TSTR + cb),
                       bf[nj][0], bf[nj][1], bf[nj][2], bf[nj][3]);
            }
            // bf regs: r0 n(0-7)k(0-15), r1 n(8-15)k(0-15),
            //          r2 n(0-7)k(16-31), r3 n(8-15)k(16-31)
#pragma unroll
            for (int mi = 0; mi < 4; mi++)
#pragma unroll
                for (int nj = 0; nj < 4; nj++) {
                    mma_fp8(acc[mi][nj * 2],     af[mi], bf[nj][0], bf[nj][2]);
                    mma_fp8(acc[mi][nj * 2 + 1], af[mi], bf[nj][1], bf[nj][3]);
                }
        }
    }

    // epilogue: relu, rescale, fp8 pairs
    const int lr = lane >> 2, lc = (lane & 3) * 2;
#pragma unroll
    for (int mi = 0; mi < 4; mi++)
#pragma unroll
        for (int ni = 0; ni < 8; ni++) {
            int m0 = bm + wm + mi * 16 + lr;
            int n0 = bn + wn + ni * 8 + lc;
            float v0 = fmaxf(acc[mi][ni][0], 0.f) * INV_SCALE;
            float v1 = fmaxf(acc[mi][ni][1], 0.f) * INV_SCALE;
            float v2 = fmaxf(acc[mi][ni][2], 0.f) * INV_SCALE;
            float v3 = fmaxf(acc[mi][ni][3], 0.f) * INV_SCALE;
            *reinterpret_cast<unsigned short*>(C + (size_t)m0 * N + n0) =
                (unsigned short)__nv_cvt_float2_to_fp8x2(
                    make_float2(v0, v1), __NV_SATFINITE, __NV_E4M3);
            *reinterpret_cast<unsigned short*>(C + (size_t)(m0 + 8) * N + n0) =
                (unsigned short)__nv_cvt_float2_to_fp8x2(
                    make_float2(v2, v3), __NV_SATFINITE, __NV_E4M3);
        }
}

// ------------------------- final: out += h3 @ Wout -------------------------
__global__ __launch_bounds__(256) void final_kernel(
    const float* __restrict__ Wout, float* __restrict__ out) {
    const int gwarp = (blockIdx.x * blockDim.x + threadIdx.x) >> 5;
    const int lane  = threadIdx.x & 31;
    if (gwarp >= cfg::B) return;
    const uint8_t* hr = g_h3 + (size_t)gwarp * cfg::H3;
    float s = 0.f;
#pragma unroll
    for (int i = lane; i < cfg::H3; i += 32)
        s += from_fp8(hr[i]) * Wout[i];
#pragma unroll
    for (int o = 16; o > 0; o >>= 1)
        s += __shfl_down_sync(0xffffffffu, s, o);
    if (lane == 0) out[gwarp] += s * INV_SCALE;
}

// ------------------------- launch ------------------------------------------
extern "C" void kernel_launch(void* const* d_in, const int* in_sizes, int n_in,
                              void* d_out, int out_size) {
    const float* dense = (const float*)d_in[0];
    const int*   sidx  = (const int*)d_in[1];
    const float* bias  = (const float*)d_in[2];
    const float* emb   = (const float*)d_in[3];
    const float* lin   = (const float*)d_in[4];
    const float* Wd    = (const float*)d_in[5];
    const float* Wld   = (const float*)d_in[6];
    const float* bld   = (const float*)d_in[7];
    const float* W1    = (const float*)d_in[8];
    const float* W2    = (const float*)d_in[9];
    const float* W3    = (const float*)d_in[10];
    const float* Wout  = (const float*)d_in[11];
    float* out = (float*)d_out;

    void *p_h, *p_h1, *p_h2, *p_h3, *p_W1, *p_W2, *p_W3;
    cudaGetSymbolAddress(&p_h,  g_h);
    cudaGetSymbolAddress(&p_h1, g_h1);
    cudaGetSymbolAddress(&p_h2, g_h2);
    cudaGetSymbolAddress(&p_h3, g_h3);
    cudaGetSymbolAddress(&p_W1, g_Wt1);
    cudaGetSymbolAddress(&p_W2, g_Wt2);
    cudaGetSymbolAddress(&p_W3, g_Wt3);

    static bool attr_done = false;
    if (!attr_done) {
        cudaFuncSetAttribute(gemm_relu_fp8,
                             cudaFuncAttributeMaxDynamicSharedMemorySize,
                             GEMM_SMEM);
        attr_done = true;
    }

    transpose_convert<<<dim3(cfg::H1 / 32, cfg::K0 / 32), 256>>>(
        W1, (uint8_t*)p_W1, cfg::K0, cfg::H1);
    transpose_convert<<<dim3(cfg::H2 / 32, cfg::H1 / 32), 256>>>(
        W2, (uint8_t*)p_W2, cfg::H1, cfg::H2);
    transpose_convert<<<dim3(cfg::H3 / 32, cfg::H2 / 32), 256>>>(
        W3, (uint8_t*)p_W3, cfg::H2, cfg::H3);

    embed_kernel<<<cfg::B / 4, 256>>>(dense, sidx, bias, emb, lin, Wd, Wld,
                                      bld, out);

    dim3 g1(cfg::H1 / BN, cfg::B / BM);
    gemm_relu_fp8<<<g1, 256, GEMM_SMEM>>>((const uint8_t*)p_h,
                                          (const uint8_t*)p_W1,
                                          (uint8_t*)p_h1,
                                          cfg::B, cfg::H1, cfg::K0);
    dim3 g2(cfg::H2 / BN, cfg::B / BM);
    gemm_relu_fp8<<<g2, 256, GEMM_SMEM>>>((const uint8_t*)p_h1,
                                          (const uint8_t*)p_W2,
                                          (uint8_t*)p_h2,
                                          cfg::B, cfg::H2, cfg::H1);
    dim3 g3(cfg::H3 / BN, cfg::B / BM);
    gemm_relu_fp8<<<g3, 256, GEMM_SMEM>>>((const uint8_t*)p_h2,
                                          (const uint8_t*)p_W3,
                                          (uint8_t*)p_h3,
                                          cfg::B, cfg::H3, cfg::H2);

    final_kernel<<<cfg::B * 32 / 256, 256>>>(Wout, out);
}

// round 6
// speedup vs baseline: 1.0723x; 1.0723x over previous
#include <cuda_runtime.h>
#include <cuda_bf16.h>
#include <cuda_fp8.h>
#include <cstdint>

// ---------------------------------------------------------------------------
// DeepFM: out = bias + first + second + MLP(emb)
// FP8 e4m3 mma.sync GEMMs; CTA tile 64x128 (128 thr, 4 warps, warp 32x64),
// NS=3 cp.async -> 4 CTAs/SM = 4 independent barrier domains.
// G3 fuses h3 @ Wout into its epilogue (atomicAdd into out).
// Scaling: act/weights fp8 of (value*64); acc = 4096*true.
// ---------------------------------------------------------------------------

namespace cfg {
constexpr int B  = 16384;
constexpr int F  = 26;
constexpr int V  = 100000;
constexpr int D  = 64;
constexpr int ND = 13;
constexpr int H1 = 1024;
constexpr int H2 = 512;
constexpr int H3 = 256;
constexpr int K0 = (F + 1) * D;  // 1728
}

constexpr float SCALE = 64.f;
constexpr float INV_SCALE = 1.f / 64.f;
constexpr float INV_SCALE2 = 1.f / 4096.f;

// ------------------------- scratch (device globals) ------------------------
__device__ uint8_t g_h  [(size_t)cfg::B * cfg::K0];   // fp8 e4m3, x64
__device__ uint8_t g_h1 [(size_t)cfg::B * cfg::H1];
__device__ uint8_t g_h2 [(size_t)cfg::B * cfg::H2];
__device__ uint8_t g_Wt1[cfg::H1 * cfg::K0];          // [N,K] fp8, x64
__device__ uint8_t g_Wt2[cfg::H2 * cfg::H1];
__device__ uint8_t g_Wt3[cfg::H3 * cfg::H2];

__device__ __forceinline__ uint8_t to_fp8(float v) {
    return (uint8_t)__nv_cvt_float_to_fp8(v, __NV_SATFINITE, __NV_E4M3);
}

// ------------------------- weight transpose+convert ------------------------
__global__ __launch_bounds__(256) void transpose_convert(
    const float* __restrict__ in, uint8_t* __restrict__ out, int K, int N) {
    __shared__ float t[32][33];
    const int tx = threadIdx.x & 31, ty = threadIdx.x >> 5;  // 32x8
    const int n0 = blockIdx.x * 32, k0 = blockIdx.y * 32;
#pragma unroll
    for (int j = 0; j < 4; j++)
        t[ty + j * 8][tx] = in[(size_t)(k0 + ty + j * 8) * N + n0 + tx];
    __syncthreads();
#pragma unroll
    for (int j = 0; j < 4; j++)
        out[(size_t)(n0 + ty + j * 8) * K + k0 + tx] =
            to_fp8(t[tx][ty + j * 8] * SCALE);
}

// ------------------------- embed + FM (fp32 exact) -------------------------
__global__ __launch_bounds__(256) void embed_kernel(
    const float* __restrict__ dense, const int* __restrict__ sidx,
    const float* __restrict__ bias, const float* __restrict__ emb_tables,
    const float* __restrict__ lin_tables, const float* __restrict__ Wd,
    const float* __restrict__ Wld, const float* __restrict__ bld,
    float* __restrict__ out) {
    const int sub = threadIdx.x >> 6;
    const int d   = threadIdx.x & 63;
    const int row = blockIdx.x * 4 + sub;

    const float* dr = dense + (size_t)row * cfg::ND;

    int idx[cfg::F];
#pragma unroll
    for (int f = 0; f < cfg::F; f++) idx[f] = __ldg(sidx + (size_t)row * cfg::F + f);

    float ev[cfg::F];
#pragma unroll
    for (int f = 0; f < cfg::F; f++)
        ev[f] = __ldg(emb_tables + ((size_t)f * cfg::V + idx[f]) * cfg::D + d);

    float lin = 0.f;
    if (d < cfg::F) lin = __ldg(lin_tables + (size_t)d * cfg::V + idx[d]);

    float de = 0.f;
#pragma unroll
    for (int i = 0; i < cfg::ND; i++) de += dr[i] * Wd[i * cfg::D + d];

    float s  = de;
    float sq = de * de;
    uint8_t* hrow = g_h + (size_t)row * cfg::K0;
    hrow[d] = to_fp8(de * SCALE);

#pragma unroll
    for (int f = 0; f < cfg::F; f++) {
        float e = ev[f];
        s  += e;
        sq += e * e;
        hrow[(size_t)(f + 1) * cfg::D + d] = to_fp8(e * SCALE);
    }

    float val = 0.5f * (s * s - sq) + lin;
    if (d < cfg::ND) val += dr[d] * Wld[d];

#pragma unroll
    for (int o = 16; o > 0; o >>= 1)
        val += __shfl_down_sync(0xffffffffu, val, o);

    __shared__ float red[8];
    if ((threadIdx.x & 31) == 0) red[threadIdx.x >> 5] = val;
    __syncthreads();
    if (d == 0)
        out[row] = bias[0] + bld[0] + red[sub * 2] + red[sub * 2 + 1];
}

// ------------------------- FP8 tensor-core GEMM ----------------------------
// CTA tile 64x128, 128 threads = 4 warps (2M x 2N), warp tile 32x64, BK=64.
// 4 CTAs/SM -> 4 independent barrier domains.
#define BM 64
#define BN 128
#define BK 64
#define NS 3
#define TSTR 80                     // 64B row + 16B pad (conflict-free)
#define A_ST (BM * TSTR)            // 5120 B / stage
#define B_ST (BN * TSTR)            // 10240 B / stage
#define STAGE_B (A_ST + B_ST)
#define GEMM_SMEM (NS * STAGE_B)    // 46080 B

__device__ __forceinline__ uint32_t smem_u32(const void* p) {
    return (uint32_t)__cvta_generic_to_shared(p);
}
__device__ __forceinline__ void cp16(uint32_t s, const void* g) {
    asm volatile("cp.async.cg.shared.global [%0], [%1], 16;\n" ::"r"(s), "l"(g));
}
__device__ __forceinline__ void cp_commit() {
    asm volatile("cp.async.commit_group;\n");
}
template <int N> __device__ __forceinline__ void cp_wait() {
    asm volatile("cp.async.wait_group %0;\n" ::"n"(N));
}
__device__ __forceinline__ void ldm_x4(uint32_t a, uint32_t& r0, uint32_t& r1,
                                       uint32_t& r2, uint32_t& r3) {
    asm volatile("ldmatrix.sync.aligned.m8n8.x4.shared.b16 {%0,%1,%2,%3}, [%4];\n"
                 : "=r"(r0), "=r"(r1), "=r"(r2), "=r"(r3)
                 : "r"(a));
}
__device__ __forceinline__ void mma_fp8(float* c, const uint32_t* a,
                                        uint32_t b0, uint32_t b1) {
    asm volatile(
        "mma.sync.aligned.m16n8k32.row.col.f32.e4m3.e4m3.f32 "
        "{%0,%1,%2,%3}, {%4,%5,%6,%7}, {%8,%9}, {%0,%1,%2,%3};\n"
        : "+f"(c[0]), "+f"(c[1]), "+f"(c[2]), "+f"(c[3])
        : "r"(a[0]), "r"(a[1]), "r"(a[2]), "r"(a[3]), "r"(b0), "r"(b1));
}

// FUSE=false: C = fp8(relu(acc)/64).  FUSE=true: out[m] += relu(acc)@Wout/4096.
template <bool FUSE>
__global__ __launch_bounds__(128, 4) void gemm_relu_fp8(
    const uint8_t* __restrict__ A, const uint8_t* __restrict__ Wt,
    uint8_t* __restrict__ C, const float* __restrict__ Wout,
    float* __restrict__ out, int M, int N, int K)
{
    extern __shared__ __align__(16) uint8_t smem[];

    const int tid  = threadIdx.x;
    const int bm   = blockIdx.y * BM;
    const int bn   = blockIdx.x * BN;
    const int wid  = tid >> 5;
    const int lane = tid & 31;
    const int wm   = (wid & 1) * 32;   // 2 warps over M
    const int wn   = (wid >> 1) * 64;  // 2 warps over N

    auto load_tiles = [&](int buf, int kofs) {
        uint8_t* sA = smem + buf * STAGE_B;
        uint8_t* sB = sA + A_ST;
        // A: 64 rows x 4 chunks of 16B (256 chunks, 2 iters)
#pragma unroll
        for (int it = 0; it < 2; it++) {
            int c = tid + it * 128;
            int r = c >> 2, cg = c & 3;
            cp16(smem_u32(sA + r * TSTR + cg * 16),
                 A + (size_t)(bm + r) * K + kofs + cg * 16);
        }
        // B: 128 n-rows x 4 chunks of 16B (512 chunks, 4 iters)
#pragma unroll
        for (int it = 0; it < 4; it++) {
            int c = tid + it * 128;
            int r = c >> 2, cg = c & 3;
            cp16(smem_u32(sB + r * TSTR + cg * 16),
                 Wt + (size_t)(bn + r) * K + kofs + cg * 16);
        }
    };

    float acc[2][8][4];
#pragma unroll
    for (int i = 0; i < 2; i++)
#pragma unroll
        for (int j = 0; j < 8; j++)
#pragma unroll
            for (int k = 0; k < 4; k++) acc[i][j][k] = 0.f;

    const int KT = K / BK;

#pragma unroll
    for (int s = 0; s < NS - 1; s++) {
        load_tiles(s, s * BK);
        cp_commit();
    }

    for (int kt = 0; kt < KT; kt++) {
        const int buf = kt % NS;
        cp_wait<NS - 2>();
        __syncthreads();

        const int pf = kt + NS - 1;
        if (pf < KT) load_tiles(pf % NS, pf * BK);
        cp_commit();

        uint8_t* sA = smem + buf * STAGE_B;
        uint8_t* sB = sA + A_ST;
#pragma unroll
        for (int ks = 0; ks < 2; ks++) {         // two k32 steps
            uint32_t af[2][4];
#pragma unroll
            for (int mi = 0; mi < 2; mi++) {
                int r = wm + mi * 16 + (lane & 15);
                int cb = ks * 32 + (lane >> 4) * 16;
                ldm_x4(smem_u32(sA + r * TSTR + cb),
                       af[mi][0], af[mi][1], af[mi][2], af[mi][3]);
            }
            uint32_t bf[4][4];
#pragma unroll
            for (int nj = 0; nj < 4; nj++) {
                int r = wn + nj * 16 + (lane & 15);
                int cb = ks * 32 + (lane >> 4) * 16;
                ldm_x4(smem_u32(sB + r * TSTR + cb),
                       bf[nj][0], bf[nj][1], bf[nj][2], bf[nj][3]);
            }
            // bf regs: r0 n(0-7)k(0-15), r1 n(8-15)k(0-15),
            //          r2 n(0-7)k(16-31), r3 n(8-15)k(16-31)
#pragma unroll
            for (int mi = 0; mi < 2; mi++)
#pragma unroll
                for (int nj = 0; nj < 4; nj++) {
                    mma_fp8(acc[mi][nj * 2],     af[mi], bf[nj][0], bf[nj][2]);
                    mma_fp8(acc[mi][nj * 2 + 1], af[mi], bf[nj][1], bf[nj][3]);
                }
        }
    }

    const int lr = lane >> 2, lc = (lane & 3) * 2;
    if (FUSE) {
        // out[m] += relu(acc) @ Wout / 4096
#pragma unroll
        for (int mi = 0; mi < 2; mi++) {
            float s0 = 0.f, s1 = 0.f;
#pragma unroll
            for (int ni = 0; ni < 8; ni++) {
                int n0 = bn + wn + ni * 8 + lc;
                float w0 = __ldg(Wout + n0);
                float w1 = __ldg(Wout + n0 + 1);
                s0 += fmaxf(acc[mi][ni][0], 0.f) * w0 +
                      fmaxf(acc[mi][ni][1], 0.f) * w1;
                s1 += fmaxf(acc[mi][ni][2], 0.f) * w0 +
                      fmaxf(acc[mi][ni][3], 0.f) * w1;
            }
            // reduce the 4 lanes sharing the same m-rows (lane = lr*4 + q)
            s0 += __shfl_xor_sync(0xffffffffu, s0, 1);
            s0 += __shfl_xor_sync(0xffffffffu, s0, 2);
            s1 += __shfl_xor_sync(0xffffffffu, s1, 1);
            s1 += __shfl_xor_sync(0xffffffffu, s1, 2);
            if ((lane & 3) == 0) {
                int m0 = bm + wm + mi * 16 + lr;
                atomicAdd(out + m0,     s0 * INV_SCALE2);
                atomicAdd(out + m0 + 8, s1 * INV_SCALE2);
            }
        }
    } else {
#pragma unroll
        for (int mi = 0; mi < 2; mi++)
#pragma unroll
            for (int ni = 0; ni < 8; ni++) {
                int m0 = bm + wm + mi * 16 + lr;
                int n0 = bn + wn + ni * 8 + lc;
                float v0 = fmaxf(acc[mi][ni][0], 0.f) * INV_SCALE;
                float v1 = fmaxf(acc[mi][ni][1], 0.f) * INV_SCALE;
                float v2 = fmaxf(acc[mi][ni][2], 0.f) * INV_SCALE;
                float v3 = fmaxf(acc[mi][ni][3], 0.f) * INV_SCALE;
                *reinterpret_cast<unsigned short*>(C + (size_t)m0 * N + n0) =
                    (unsigned short)__nv_cvt_float2_to_fp8x2(
                        make_float2(v0, v1), __NV_SATFINITE, __NV_E4M3);
                *reinterpret_cast<unsigned short*>(C + (size_t)(m0 + 8) * N + n0) =
                    (unsigned short)__nv_cvt_float2_to_fp8x2(
                        make_float2(v2, v3), __NV_SATFINITE, __NV_E4M3);
            }
    }
}

// ------------------------- launch ------------------------------------------
extern "C" void kernel_launch(void* const* d_in, const int* in_sizes, int n_in,
                              void* d_out, int out_size) {
    const float* dense = (const float*)d_in[0];
    const int*   sidx  = (const int*)d_in[1];
    const float* bias  = (const float*)d_in[2];
    const float* emb   = (const float*)d_in[3];
    const float* lin   = (const float*)d_in[4];
    const float* Wd    = (const float*)d_in[5];
    const float* Wld   = (const float*)d_in[6];
    const float* bld   = (const float*)d_in[7];
    const float* W1    = (const float*)d_in[8];
    const float* W2    = (const float*)d_in[9];
    const float* W3    = (const float*)d_in[10];
    const float* Wout  = (const float*)d_in[11];
    float* out = (float*)d_out;

    void *p_h, *p_h1, *p_h2, *p_W1, *p_W2, *p_W3;
    cudaGetSymbolAddress(&p_h,  g_h);
    cudaGetSymbolAddress(&p_h1, g_h1);
    cudaGetSymbolAddress(&p_h2, g_h2);
    cudaGetSymbolAddress(&p_W1, g_Wt1);
    cudaGetSymbolAddress(&p_W2, g_Wt2);
    cudaGetSymbolAddress(&p_W3, g_Wt3);

    static bool attr_done = false;
    if (!attr_done) {
        cudaFuncSetAttribute(gemm_relu_fp8<false>,
                             cudaFuncAttributeMaxDynamicSharedMemorySize,
                             GEMM_SMEM);
        cudaFuncSetAttribute(gemm_relu_fp8<true>,
                             cudaFuncAttributeMaxDynamicSharedMemorySize,
                             GEMM_SMEM);
        attr_done = true;
    }

    transpose_convert<<<dim3(cfg::H1 / 32, cfg::K0 / 32), 256>>>(
        W1, (uint8_t*)p_W1, cfg::K0, cfg::H1);
    transpose_convert<<<dim3(cfg::H2 / 32, cfg::H1 / 32), 256>>>(
        W2, (uint8_t*)p_W2, cfg::H1, cfg::H2);
    transpose_convert<<<dim3(cfg::H3 / 32, cfg::H2 / 32), 256>>>(
        W3, (uint8_t*)p_W3, cfg::H2, cfg::H3);

    embed_kernel<<<cfg::B / 4, 256>>>(dense, sidx, bias, emb, lin, Wd, Wld,
                                      bld, out);

    dim3 g1(cfg::H1 / BN, cfg::B / BM);
    gemm_relu_fp8<false><<<g1, 128, GEMM_SMEM>>>(
        (const uint8_t*)p_h, (const uint8_t*)p_W1, (uint8_t*)p_h1,
        nullptr, nullptr, cfg::B, cfg::H1, cfg::K0);
    dim3 g2(cfg::H2 / BN, cfg::B / BM);
    gemm_relu_fp8<false><<<g2, 128, GEMM_SMEM>>>(
        (const uint8_t*)p_h1, (const uint8_t*)p_W2, (uint8_t*)p_h2,
        nullptr, nullptr, cfg::B, cfg::H2, cfg::H1);
    dim3 g3(cfg::H3 / BN, cfg::B / BM);
    gemm_relu_fp8<true><<<g3, 128, GEMM_SMEM>>>(
        (const uint8_t*)p_h2, (const uint8_t*)p_W3, nullptr,
        Wout, out, cfg::B, cfg::H3, cfg::H2);
}